// round 2
// baseline (speedup 1.0000x reference)
#include <cuda_runtime.h>
#include <math.h>

#define BB 64
#define TT 512
#define DD 512
#define HH 1024

// Scratch (static device globals — allocation-free kernel_launch)
__device__ float g_XG[3 * TT * BB * HH];   // [g][t][b][h]  precomputed x-projections (+ input bias)
__device__ float g_Wt[3 * HH * HH];        // [g][j][k]     transposed recurrent weights
__device__ float g_h[2][BB * HH];          // ping-pong hidden state

// ---------------------------------------------------------------------------
// Transpose W_zh/W_rh/W_nh ([k][j] -> [j][k]) so step-kernel dots are k-contiguous
// ---------------------------------------------------------------------------
__global__ void transpose_kernel(const float* __restrict__ Wz,
                                 const float* __restrict__ Wr,
                                 const float* __restrict__ Wn) {
    int g = blockIdx.z;
    const float* src = (g == 0) ? Wz : ((g == 1) ? Wr : Wn);
    __shared__ float tile[32][33];
    int tx = threadIdx.x;
    int j0 = blockIdx.x * 32;
    int k0 = blockIdx.y * 32;
    for (int i = threadIdx.y; i < 32; i += 8)
        tile[i][tx] = src[(k0 + i) * HH + (j0 + tx)];
    __syncthreads();
    for (int i = threadIdx.y; i < 32; i += 8)
        g_Wt[g * HH * HH + (j0 + i) * HH + (k0 + tx)] = tile[tx][i];
}

// ---------------------------------------------------------------------------
// h0 = 0
// ---------------------------------------------------------------------------
__global__ void init_h() {
    int i = blockIdx.x * blockDim.x + threadIdx.x;
    if (i < BB * HH) g_h[0][i] = 0.0f;
}

// ---------------------------------------------------------------------------
// Precompute xg[g][t][b][:] = x[b][t][:] @ W_gx + b_gx   (classic 128x128x16 sgemm)
// ---------------------------------------------------------------------------
__global__ __launch_bounds__(256) void xproj_kernel(
    const float* __restrict__ x,
    const float* __restrict__ Wz, const float* __restrict__ Wr, const float* __restrict__ Wn,
    const float* __restrict__ bz, const float* __restrict__ br, const float* __restrict__ bn) {

    int g = blockIdx.z;
    const float* Wm   = (g == 0) ? Wz : ((g == 1) ? Wr : Wn);
    const float* bias = (g == 0) ? bz : ((g == 1) ? br : bn);

    __shared__ float As[16][128];   // [k][m]
    __shared__ float Bs[16][128];   // [k][n]

    int m0 = blockIdx.x * 128;
    int n0 = blockIdx.y * 128;
    int tid = threadIdx.x;
    int txq = tid % 16, tyq = tid / 16;

    float acc[8][8];
#pragma unroll
    for (int i = 0; i < 8; i++)
#pragma unroll
        for (int j = 0; j < 8; j++) acc[i][j] = 0.0f;

    for (int k0 = 0; k0 < DD; k0 += 16) {
        // A tile: 128 rows x 16 k  (512 float4)
#pragma unroll
        for (int l = 0; l < 2; l++) {
            int idx = tid + l * 256;
            int row = idx >> 2;
            int kk  = (idx & 3) * 4;
            float4 v = *(const float4*)&x[(size_t)(m0 + row) * DD + k0 + kk];
            As[kk + 0][row] = v.x;
            As[kk + 1][row] = v.y;
            As[kk + 2][row] = v.z;
            As[kk + 3][row] = v.w;
        }
        // B tile: 16 k x 128 n (512 float4), coalesced
#pragma unroll
        for (int l = 0; l < 2; l++) {
            int idx = tid + l * 256;
            int row = idx >> 5;
            int nn  = (idx & 31) * 4;
            *(float4*)&Bs[row][nn] = *(const float4*)&Wm[(size_t)(k0 + row) * HH + n0 + nn];
        }
        __syncthreads();
#pragma unroll
        for (int k = 0; k < 16; k++) {
            float a[8], b[8];
            float4 a0 = *(const float4*)&As[k][tyq * 8];
            float4 a1 = *(const float4*)&As[k][tyq * 8 + 4];
            float4 b0 = *(const float4*)&Bs[k][txq * 8];
            float4 b1 = *(const float4*)&Bs[k][txq * 8 + 4];
            a[0]=a0.x; a[1]=a0.y; a[2]=a0.z; a[3]=a0.w; a[4]=a1.x; a[5]=a1.y; a[6]=a1.z; a[7]=a1.w;
            b[0]=b0.x; b[1]=b0.y; b[2]=b0.z; b[3]=b0.w; b[4]=b1.x; b[5]=b1.y; b[6]=b1.z; b[7]=b1.w;
#pragma unroll
            for (int i = 0; i < 8; i++)
#pragma unroll
                for (int j = 0; j < 8; j++) acc[i][j] += a[i] * b[j];
        }
        __syncthreads();
    }

    // write out: row m = b*T + t  ->  g_XG[g][t][b][n]
#pragma unroll
    for (int i = 0; i < 8; i++) {
        int m  = m0 + tyq * 8 + i;
        int bb = m / TT;
        int tt = m % TT;
        float* outr = &g_XG[(((size_t)g * TT + tt) * BB + bb) * HH + n0 + txq * 8];
#pragma unroll
        for (int j = 0; j < 8; j++)
            outr[j] = acc[i][j] + bias[n0 + txq * 8 + j];
    }
}

// ---------------------------------------------------------------------------
// One recurrence step. Grid = 128 CTAs (8 output columns each), 256 threads.
// Each thread: 2 batch rows x 3 gates -> 6 float4 accumulators over K=1024.
// ---------------------------------------------------------------------------
#define BKH 128
#define HS_STRIDE 132

__device__ __forceinline__ float hsum4(float4 v) { return (v.x + v.y) + (v.z + v.w); }

__global__ __launch_bounds__(256) void step_kernel(
    int t, float* __restrict__ final_out,
    const float* __restrict__ bzh, const float* __restrict__ brh, const float* __restrict__ bnh) {

    const float* __restrict__ h_in = g_h[t & 1];
    float* __restrict__ h_out = (t == TT - 1) ? final_out : g_h[(t + 1) & 1];

    __shared__ float hs[BB * HS_STRIDE];        // h chunk  [b][k] padded
    __shared__ float ws[3 * 8 * HS_STRIDE];     // W chunk  [g][jl][k] padded

    int tid = threadIdx.x;
    int jl  = tid & 7;
    int brr = tid >> 3;            // 0..31
    int j   = blockIdx.x * 8 + jl;
    int b0  = brr;
    int b1  = brr + 32;

    float4 az0 = {0,0,0,0}, az1 = az0, ar0 = az0, ar1 = az0, an0 = az0, an1 = az0;

    for (int kc = 0; kc < HH; kc += BKH) {
        // stage h[0:64][kc:kc+128]
#pragma unroll
        for (int l = 0; l < 8; l++) {
            int idx = tid + l * 256;       // 2048 float4
            int row = idx >> 5;
            int c   = idx & 31;
            float4 v = *(const float4*)&h_in[row * HH + kc + c * 4];
            *(float4*)&hs[row * HS_STRIDE + c * 4] = v;
        }
        // stage W[g][j0..j0+7][kc:kc+128] for 3 gates (768 float4)
#pragma unroll
        for (int l = 0; l < 3; l++) {
            int idx  = tid + l * 256;
            int row  = idx >> 5;          // 0..23 = g*8 + jrow
            int c    = idx & 31;
            int gg   = row >> 3;
            int jrow = row & 7;
            float4 v = *(const float4*)&g_Wt[((size_t)gg * HH + blockIdx.x * 8 + jrow) * HH + kc + c * 4];
            *(float4*)&ws[row * HS_STRIDE + c * 4] = v;
        }
        __syncthreads();

        const float4* h0p = (const float4*)&hs[b0 * HS_STRIDE];
        const float4* h1p = (const float4*)&hs[b1 * HS_STRIDE];
        const float4* wzp = (const float4*)&ws[(0 * 8 + jl) * HS_STRIDE];
        const float4* wrp = (const float4*)&ws[(1 * 8 + jl) * HS_STRIDE];
        const float4* wnp = (const float4*)&ws[(2 * 8 + jl) * HS_STRIDE];

#pragma unroll 4
        for (int k4 = 0; k4 < BKH / 4; k4++) {
            float4 hv0 = h0p[k4];
            float4 hv1 = h1p[k4];
            float4 wzv = wzp[k4];
            float4 wrv = wrp[k4];
            float4 wnv = wnp[k4];
            az0.x += hv0.x * wzv.x; az0.y += hv0.y * wzv.y; az0.z += hv0.z * wzv.z; az0.w += hv0.w * wzv.w;
            az1.x += hv1.x * wzv.x; az1.y += hv1.y * wzv.y; az1.z += hv1.z * wzv.z; az1.w += hv1.w * wzv.w;
            ar0.x += hv0.x * wrv.x; ar0.y += hv0.y * wrv.y; ar0.z += hv0.z * wrv.z; ar0.w += hv0.w * wrv.w;
            ar1.x += hv1.x * wrv.x; ar1.y += hv1.y * wrv.y; ar1.z += hv1.z * wrv.z; ar1.w += hv1.w * wrv.w;
            an0.x += hv0.x * wnv.x; an0.y += hv0.y * wnv.y; an0.z += hv0.z * wnv.z; an0.w += hv0.w * wnv.w;
            an1.x += hv1.x * wnv.x; an1.y += hv1.y * wnv.y; an1.z += hv1.z * wnv.z; an1.w += hv1.w * wnv.w;
        }
        __syncthreads();
    }

    float hz0 = hsum4(az0), hz1 = hsum4(az1);
    float hr0 = hsum4(ar0), hr1 = hsum4(ar1);
    float hn0 = hsum4(an0), hn1 = hsum4(an1);

    const float* xzt = g_XG + ((size_t)(0 * TT + t)) * (BB * HH);
    const float* xrt = g_XG + ((size_t)(1 * TT + t)) * (BB * HH);
    const float* xnt = g_XG + ((size_t)(2 * TT + t)) * (BB * HH);

    float bz = bzh[j], brv = brh[j], bn = bnh[j];

    {
        float z = 1.0f / (1.0f + __expf(-(xzt[b0 * HH + j] + hz0 + bz)));
        float r = 1.0f / (1.0f + __expf(-(xrt[b0 * HH + j] + hr0 + brv)));
        float n = tanhf(xnt[b0 * HH + j] + r * (hn0 + bn));
        h_out[b0 * HH + j] = (1.0f - z) * n + z * h_in[b0 * HH + j];
    }
    {
        float z = 1.0f / (1.0f + __expf(-(xzt[b1 * HH + j] + hz1 + bz)));
        float r = 1.0f / (1.0f + __expf(-(xrt[b1 * HH + j] + hr1 + brv)));
        float n = tanhf(xnt[b1 * HH + j] + r * (hn1 + bn));
        h_out[b1 * HH + j] = (1.0f - z) * n + z * h_in[b1 * HH + j];
    }
}

// ---------------------------------------------------------------------------
extern "C" void kernel_launch(void* const* d_in, const int* in_sizes, int n_in,
                              void* d_out, int out_size) {
    const float* x    = (const float*)d_in[0];
    const float* W_zx = (const float*)d_in[1];
    const float* W_zh = (const float*)d_in[2];
    const float* W_rx = (const float*)d_in[3];
    const float* W_rh = (const float*)d_in[4];
    const float* W_nx = (const float*)d_in[5];
    const float* W_nh = (const float*)d_in[6];
    const float* b_zx = (const float*)d_in[7];
    const float* b_zh = (const float*)d_in[8];
    const float* b_rx = (const float*)d_in[9];
    const float* b_rh = (const float*)d_in[10];
    const float* b_nx = (const float*)d_in[11];
    const float* b_nh = (const float*)d_in[12];
    float* out = (float*)d_out;

    transpose_kernel<<<dim3(HH / 32, HH / 32, 3), dim3(32, 8)>>>(W_zh, W_rh, W_nh);
    init_h<<<(BB * HH + 255) / 256, 256>>>();
    xproj_kernel<<<dim3((BB * TT) / 128, HH / 128, 3), 256>>>(x, W_zx, W_rx, W_nx, b_zx, b_rx, b_nx);

    for (int t = 0; t < TT; t++)
        step_kernel<<<HH / 8, 256>>>(t, out, b_zh, b_rh, b_nh);
}

// round 3
// speedup vs baseline: 1.2760x; 1.2760x over previous
#include <cuda_runtime.h>
#include <math.h>

#define BB 64
#define TT 512
#define DD 512
#define HH 1024

#define NCTA    128
#define JB      16          // j columns per CTA
#define BHALF   32          // batch rows per CTA
#define HSS     132         // hs row stride in floats (16B-aligned, conflict-free)
#define NKP     (HH / 2)    // 512 k-pairs total
#define CHUNK_K 128         // k per staged chunk
#define NCHUNK  (HH / CHUNK_K)
#define KP_CHUNK (CHUNK_K / 2)

#define WS_FLOATS (3 * NKP * JB * 2)          // 49152
#define HS_FLOATS (BHALF * HSS)               // 4224
#define SMEM_BYTES ((WS_FLOATS + HS_FLOATS) * 4)

typedef unsigned long long u64;

// Scratch (static device globals — allocation-free kernel_launch)
__device__ float g_XG[3 * TT * BB * HH];   // [g][t][b][h] precomputed x-projections (+ input bias)
__device__ float g_h[2][BB * HH];          // ping-pong hidden state
__device__ unsigned int g_bar_count = 0;
__device__ volatile unsigned int g_bar_gen = 0;

__device__ __forceinline__ void ffma2(u64& d, u64 a, u64 b) {
    asm("fma.rn.f32x2 %0, %1, %2, %0;" : "+l"(d) : "l"(a), "l"(b));
}
__device__ __forceinline__ float pairsum(u64 v) {
    return __uint_as_float((unsigned)(v & 0xffffffffull)) +
           __uint_as_float((unsigned)(v >> 32));
}

// All 128 CTAs are co-resident (grid <= #SMs, 1 CTA/SM) -> spin barrier is safe.
__device__ __forceinline__ void grid_barrier() {
    __syncthreads();
    if (threadIdx.x == 0) {
        __threadfence();                       // publish h writes
        unsigned gen = g_bar_gen;
        if (atomicAdd(&g_bar_count, 1u) == NCTA - 1) {
            g_bar_count = 0;
            __threadfence();
            g_bar_gen = gen + 1;
        } else {
            while (g_bar_gen == gen) { }
        }
        __threadfence();
    }
    __syncthreads();
}

// ---------------------------------------------------------------------------
// Precompute xg[g][t][b][:] = x[b][t][:] @ W_gx + b_gx  (128x128x16 sgemm)
// ---------------------------------------------------------------------------
__global__ __launch_bounds__(256) void xproj_kernel(
    const float* __restrict__ x,
    const float* __restrict__ Wz, const float* __restrict__ Wr, const float* __restrict__ Wn,
    const float* __restrict__ bz, const float* __restrict__ br, const float* __restrict__ bn) {

    int g = blockIdx.z;
    const float* Wm   = (g == 0) ? Wz : ((g == 1) ? Wr : Wn);
    const float* bias = (g == 0) ? bz : ((g == 1) ? br : bn);

    __shared__ float As[16][128];   // [k][m]
    __shared__ float Bs[16][128];   // [k][n]

    int m0 = blockIdx.x * 128;
    int n0 = blockIdx.y * 128;
    int tid = threadIdx.x;
    int txq = tid % 16, tyq = tid / 16;

    float acc[8][8];
#pragma unroll
    for (int i = 0; i < 8; i++)
#pragma unroll
        for (int j = 0; j < 8; j++) acc[i][j] = 0.0f;

    for (int k0 = 0; k0 < DD; k0 += 16) {
#pragma unroll
        for (int l = 0; l < 2; l++) {
            int idx = tid + l * 256;
            int row = idx >> 2;
            int kk  = (idx & 3) * 4;
            float4 v = *(const float4*)&x[(size_t)(m0 + row) * DD + k0 + kk];
            As[kk + 0][row] = v.x;
            As[kk + 1][row] = v.y;
            As[kk + 2][row] = v.z;
            As[kk + 3][row] = v.w;
        }
#pragma unroll
        for (int l = 0; l < 2; l++) {
            int idx = tid + l * 256;
            int row = idx >> 5;
            int nn  = (idx & 31) * 4;
            *(float4*)&Bs[row][nn] = *(const float4*)&Wm[(size_t)(k0 + row) * HH + n0 + nn];
        }
        __syncthreads();
#pragma unroll
        for (int k = 0; k < 16; k++) {
            float a[8], b[8];
            float4 a0 = *(const float4*)&As[k][tyq * 8];
            float4 a1 = *(const float4*)&As[k][tyq * 8 + 4];
            float4 b0 = *(const float4*)&Bs[k][txq * 8];
            float4 b1 = *(const float4*)&Bs[k][txq * 8 + 4];
            a[0]=a0.x; a[1]=a0.y; a[2]=a0.z; a[3]=a0.w; a[4]=a1.x; a[5]=a1.y; a[6]=a1.z; a[7]=a1.w;
            b[0]=b0.x; b[1]=b0.y; b[2]=b0.z; b[3]=b0.w; b[4]=b1.x; b[5]=b1.y; b[6]=b1.z; b[7]=b1.w;
#pragma unroll
            for (int i = 0; i < 8; i++)
#pragma unroll
                for (int j = 0; j < 8; j++) acc[i][j] += a[i] * b[j];
        }
        __syncthreads();
    }

#pragma unroll
    for (int i = 0; i < 8; i++) {
        int m  = m0 + tyq * 8 + i;
        int bb = m / TT;
        int tt = m % TT;
        float* outr = &g_XG[(((size_t)g * TT + tt) * BB + bb) * HH + n0 + txq * 8];
#pragma unroll
        for (int j = 0; j < 8; j++)
            outr[j] = acc[i][j] + bias[n0 + txq * 8 + j];
    }
}

// ---------------------------------------------------------------------------
// Persistent GRU scan. 128 CTAs = 64 j-blocks x 2 batch-halves. W resident in
// SMEM for all 512 steps; h ping-pongs in global (L2) via ldcg/stcg; one grid
// barrier per step. Inner product uses packed fma.rn.f32x2.
// ---------------------------------------------------------------------------
__global__ __launch_bounds__(256, 1) void gru_scan_kernel(
    float* __restrict__ out,
    const float* __restrict__ Wzh, const float* __restrict__ Wrh, const float* __restrict__ Wnh,
    const float* __restrict__ bzh, const float* __restrict__ brh, const float* __restrict__ bnh)
{
    extern __shared__ float smem[];
    float* ws = smem;                    // [g][kp][j][2]  (u64-friendly)
    float* hs = smem + WS_FLOATS;        // [b_local][HSS]

    const int tid  = threadIdx.x;
    const int jb   = blockIdx.x & 63;
    const int bb   = blockIdx.x >> 6;
    const int warp = tid >> 5;
    const int lane = tid & 31;
    const int j    = lane & 15;
    const int bsub = lane >> 4;
    const int r0l  = warp * 4 + bsub * 2;     // local batch row (and +1)
    const int jcol = jb * JB + j;
    const int row0 = bb * BHALF + r0l;        // global batch rows row0, row0+1

    // ---- load this CTA's W slice into SMEM (once per kernel) ----
    {
        for (int e = tid; e < 3 * HH * JB; e += 256) {
            int jj = e & (JB - 1);
            int k  = (e >> 4) & (HH - 1);
            int g  = e >> 14;
            const float* Wsrc = (g == 0) ? Wzh : ((g == 1) ? Wrh : Wnh);
            ws[((g * NKP + (k >> 1)) * JB + jj) * 2 + (k & 1)] =
                Wsrc[(size_t)k * HH + jb * JB + jj];
        }
    }
    // ---- zero h[0] (disjoint slices across CTAs) ----
    for (int e = tid; e < (BB * HH) / NCTA; e += 256)
        g_h[0][blockIdx.x * ((BB * HH) / NCTA) + e] = 0.0f;
    grid_barrier();

    const float bz = bzh[jcol], br = brh[jcol], bn = bnh[jcol];

    const u64* ws8    = (const u64*)ws;
    const u64* h0base = (const u64*)(hs + r0l * HSS);
    const u64* h1base = (const u64*)(hs + (r0l + 1) * HSS);

    for (int t = 0; t < TT; t++) {
        const float* __restrict__ h_in  = g_h[t & 1];
        float* __restrict__ h_out = (t == TT - 1) ? out : g_h[(t + 1) & 1];

        // prefetch epilogue operands (consumed after the K loop; latency hidden)
        const float* xz = g_XG + ((size_t)(0 * TT + t)) * (BB * HH);
        const float* xr = g_XG + ((size_t)(1 * TT + t)) * (BB * HH);
        const float* xn = g_XG + ((size_t)(2 * TT + t)) * (BB * HH);
        float xz0 = xz[(size_t)row0 * HH + jcol], xz1 = xz[(size_t)(row0 + 1) * HH + jcol];
        float xr0 = xr[(size_t)row0 * HH + jcol], xr1 = xr[(size_t)(row0 + 1) * HH + jcol];
        float xn0 = xn[(size_t)row0 * HH + jcol], xn1 = xn[(size_t)(row0 + 1) * HH + jcol];
        float hp0 = __ldcg(&h_in[(size_t)row0 * HH + jcol]);
        float hp1 = __ldcg(&h_in[(size_t)(row0 + 1) * HH + jcol]);

        u64 az0 = 0, az1 = 0, ar0 = 0, ar1 = 0, an0 = 0, an1 = 0;

        // register-double-buffered h staging: 4 float4 per thread per chunk
        float4 pf[4];
        {
            const int c4 = lane * 4;
#pragma unroll
            for (int l = 0; l < 4; l++) {
                int rowl = warp + l * 8;
                pf[l] = __ldcg((const float4*)&h_in[(size_t)(bb * BHALF + rowl) * HH + 0 + c4]);
            }
        }

        for (int ch = 0; ch < NCHUNK; ch++) {
            __syncthreads();                 // hs free (prev chunk consumed)
            {
                const int c4 = lane * 4;
#pragma unroll
                for (int l = 0; l < 4; l++) {
                    int rowl = warp + l * 8;
                    *(float4*)&hs[rowl * HSS + c4] = pf[l];
                }
            }
            __syncthreads();
            if (ch + 1 < NCHUNK) {
                const int kcn = (ch + 1) * CHUNK_K;
                const int c4 = lane * 4;
#pragma unroll
                for (int l = 0; l < 4; l++) {
                    int rowl = warp + l * 8;
                    pf[l] = __ldcg((const float4*)&h_in[(size_t)(bb * BHALF + rowl) * HH + kcn + c4]);
                }
            }

            const int kp0 = ch * KP_CHUNK;
            const u64* wz = ws8 + ((size_t)(0 * NKP) + kp0) * JB + j;
            const u64* wr = ws8 + ((size_t)(1 * NKP) + kp0) * JB + j;
            const u64* wn = ws8 + ((size_t)(2 * NKP) + kp0) * JB + j;

#pragma unroll
            for (int kpl = 0; kpl < KP_CHUNK; kpl++) {
                u64 hv0 = h0base[kpl];
                u64 hv1 = h1base[kpl];
                u64 wzv = wz[(size_t)kpl * JB];
                u64 wrv = wr[(size_t)kpl * JB];
                u64 wnv = wn[(size_t)kpl * JB];
                ffma2(az0, hv0, wzv); ffma2(az1, hv1, wzv);
                ffma2(ar0, hv0, wrv); ffma2(ar1, hv1, wrv);
                ffma2(an0, hv0, wnv); ffma2(an1, hv1, wnv);
            }
        }

        // epilogue: gate math for (row0, jcol) and (row0+1, jcol)
        float hz0 = pairsum(az0), hz1 = pairsum(az1);
        float hr0 = pairsum(ar0), hr1 = pairsum(ar1);
        float hn0 = pairsum(an0), hn1 = pairsum(an1);

        {
            float z = 1.0f / (1.0f + __expf(-(xz0 + hz0 + bz)));
            float r = 1.0f / (1.0f + __expf(-(xr0 + hr0 + br)));
            float n = tanhf(xn0 + r * (hn0 + bn));
            __stcg(&h_out[(size_t)row0 * HH + jcol], (1.0f - z) * n + z * hp0);
        }
        {
            float z = 1.0f / (1.0f + __expf(-(xz1 + hz1 + bz)));
            float r = 1.0f / (1.0f + __expf(-(xr1 + hr1 + br)));
            float n = tanhf(xn1 + r * (hn1 + bn));
            __stcg(&h_out[(size_t)(row0 + 1) * HH + jcol], (1.0f - z) * n + z * hp1);
        }

        grid_barrier();
    }
}

// ---------------------------------------------------------------------------
extern "C" void kernel_launch(void* const* d_in, const int* in_sizes, int n_in,
                              void* d_out, int out_size) {
    const float* x    = (const float*)d_in[0];
    const float* W_zx = (const float*)d_in[1];
    const float* W_zh = (const float*)d_in[2];
    const float* W_rx = (const float*)d_in[3];
    const float* W_rh = (const float*)d_in[4];
    const float* W_nx = (const float*)d_in[5];
    const float* W_nh = (const float*)d_in[6];
    const float* b_zx = (const float*)d_in[7];
    const float* b_zh = (const float*)d_in[8];
    const float* b_rx = (const float*)d_in[9];
    const float* b_rh = (const float*)d_in[10];
    const float* b_nx = (const float*)d_in[11];
    const float* b_nh = (const float*)d_in[12];
    float* out = (float*)d_out;

    cudaFuncSetAttribute(gru_scan_kernel,
                         cudaFuncAttributeMaxDynamicSharedMemorySize, SMEM_BYTES);

    xproj_kernel<<<dim3((BB * TT) / 128, HH / 128, 3), 256>>>(
        x, W_zx, W_rx, W_nx, b_zx, b_rx, b_nx);

    gru_scan_kernel<<<NCTA, 256, SMEM_BYTES>>>(
        out, W_zh, W_rh, W_nh, b_zh, b_rh, b_nh);
}